// round 1
// baseline (speedup 1.0000x reference)
#include <cuda_runtime.h>
#include <cuda_bf16.h>
#include <cstdint>

#define NC  100000
#define NT  100000
#define NNZ 640000
#define D   128

// One warp per nonzero. Each lane handles one float4 (4 floats) of the D=128 row.
// Gather mat[col] (float4 per lane), reduce-add into out[row] via red.global.add.v4.f32
// (no-return atomic -> REDG pipe, no result latency on the critical path).
__global__ __launch_bounds__(256) void scatter_add_kernel(
    const float4* __restrict__ mat,   // [NT, 32] as float4
    const int*    __restrict__ row,   // [NNZ]
    const int*    __restrict__ col,   // [NNZ]
    float4*       __restrict__ out)   // [NC, 32] as float4
{
    const int gtid = blockIdx.x * blockDim.x + threadIdx.x;
    const int nz   = gtid >> 5;        // warp id == nonzero id
    const int lane = threadIdx.x & 31;
    if (nz >= NNZ) return;

    // Same-address loads in a warp broadcast from L1 — cheap.
    const int r = __ldg(row + nz);
    const int c = __ldg(col + nz);

    const float4 v = __ldg(mat + (size_t)c * (D / 4) + lane);

    float* dst = reinterpret_cast<float*>(out + (size_t)r * (D / 4) + lane);
    asm volatile(
        "red.global.add.v4.f32 [%0], {%1, %2, %3, %4};"
        :: "l"(dst), "f"(v.x), "f"(v.y), "f"(v.z), "f"(v.w)
        : "memory");
}

extern "C" void kernel_launch(void* const* d_in, const int* in_sizes, int n_in,
                              void* d_out, int out_size) {
    const float4* mat = (const float4*)d_in[0];
    const int*    row = (const int*)d_in[1];
    const int*    col = (const int*)d_in[2];
    float4*       out = (float4*)d_out;

    // Output is poisoned by the harness — zero it first (memset node is
    // graph-capturable on the capture stream).
    cudaMemsetAsync(d_out, 0, (size_t)out_size * sizeof(float));

    // One warp per nonzero: NNZ * 32 threads.
    const int threads = 256;
    const long long total = (long long)NNZ * 32;
    const int blocks = (int)((total + threads - 1) / threads);
    scatter_add_kernel<<<blocks, threads>>>(mat, row, col, out);
}

// round 2
// speedup vs baseline: 1.4807x; 1.4807x over previous
#include <cuda_runtime.h>
#include <cuda_bf16.h>
#include <cstdint>

#define NC  100000
#define NT  100000
#define NNZ 640000
#define D   128

// ---- counting-sort scratch (device globals: no allocation allowed) ----
#define SCAN_T   512
#define SCAN_NB  ((NC + SCAN_T - 1) / SCAN_T)   // 196

__device__ int g_cnt[NC];          // per-row nnz histogram
__device__ int g_ptr[NC + 1];      // CSR row pointers (exclusive scan)
__device__ int g_cursor[NC];       // scatter cursors (init = ptr)
__device__ int g_scol[NNZ];        // col indices grouped by row
__device__ int g_bsum[SCAN_NB];    // per-block sums for scan
__device__ int g_boff[SCAN_NB];    // exclusive block offsets

// Phase 0: zero the histogram (graph replays reuse the globals).
__global__ void zero_cnt_kernel() {
    int i = blockIdx.x * blockDim.x + threadIdx.x;
    if (i < NC) g_cnt[i] = 0;
}

// Phase 1: histogram rows.
__global__ __launch_bounds__(256) void hist_kernel(const int* __restrict__ row) {
    int i = blockIdx.x * blockDim.x + threadIdx.x;
    if (i < NNZ) atomicAdd(&g_cnt[row[i]], 1);
}

// Phase 2a: per-block sums of the histogram.
__global__ __launch_bounds__(SCAN_T) void scan_blocksum_kernel() {
    __shared__ int s[SCAN_T];
    int i = blockIdx.x * SCAN_T + threadIdx.x;
    s[threadIdx.x] = (i < NC) ? g_cnt[i] : 0;
    __syncthreads();
    for (int off = SCAN_T / 2; off > 0; off >>= 1) {
        if (threadIdx.x < off) s[threadIdx.x] += s[threadIdx.x + off];
        __syncthreads();
    }
    if (threadIdx.x == 0) g_bsum[blockIdx.x] = s[0];
}

// Phase 2b: exclusive scan of block sums (single block; SCAN_NB=196 <= 256).
__global__ __launch_bounds__(256) void scan_toplevel_kernel() {
    __shared__ int s[256];
    int t = threadIdx.x;
    int v = (t < SCAN_NB) ? g_bsum[t] : 0;
    s[t] = v;
    __syncthreads();
    // Hillis-Steele inclusive scan
    for (int off = 1; off < 256; off <<= 1) {
        int add = (t >= off) ? s[t - off] : 0;
        __syncthreads();
        s[t] += add;
        __syncthreads();
    }
    if (t < SCAN_NB) g_boff[t] = s[t] - v;   // exclusive
}

// Phase 2c: block-local exclusive scan + offset -> ptr & cursor.
__global__ __launch_bounds__(SCAN_T) void scan_final_kernel() {
    __shared__ int s[SCAN_T];
    int t = threadIdx.x;
    int i = blockIdx.x * SCAN_T + t;
    int v = (i < NC) ? g_cnt[i] : 0;
    s[t] = v;
    __syncthreads();
    for (int off = 1; off < SCAN_T; off <<= 1) {
        int add = (t >= off) ? s[t - off] : 0;
        __syncthreads();
        s[t] += add;
        __syncthreads();
    }
    if (i < NC) {
        int excl = g_boff[blockIdx.x] + s[t] - v;
        g_ptr[i]    = excl;
        g_cursor[i] = excl;
    }
    if (i == NC - 1) g_ptr[NC] = NNZ;
}

// Phase 3: scatter col indices into row-grouped order.
__global__ __launch_bounds__(256) void scatter_idx_kernel(
    const int* __restrict__ row, const int* __restrict__ col) {
    int i = blockIdx.x * blockDim.x + threadIdx.x;
    if (i < NNZ) {
        int r = row[i];
        int pos = atomicAdd(&g_cursor[r], 1);
        g_scol[pos] = col[i];
    }
}

// Phase 4: one warp per output row. Each lane owns one float4 (D=128 -> 32
// lanes x 16B). Col indices prefetched per-lane and shfl-broadcast so the
// float4 gathers issue back-to-back (high MLP), then one plain store.
// No atomics, no memset: every row gets written (zeros for empty rows).
__global__ __launch_bounds__(256) void gather_sum_kernel(
    const float4* __restrict__ mat, float4* __restrict__ out) {
    int gwarp = (blockIdx.x * blockDim.x + threadIdx.x) >> 5;
    int lane  = threadIdx.x & 31;
    if (gwarp >= NC) return;

    int start = g_ptr[gwarp];
    int end   = g_ptr[gwarp + 1];
    int n     = end - start;

    float4 acc = make_float4(0.f, 0.f, 0.f, 0.f);

    int i = 0;
    while (i < n) {
        int chunk = n - i;
        if (chunk > 32) chunk = 32;
        int cj = (lane < chunk) ? __ldg(g_scol + start + i + lane) : 0;
        #pragma unroll 4
        for (int j = 0; j < chunk; ++j) {
            int c = __shfl_sync(0xffffffffu, cj, j);
            float4 v = __ldg(mat + (size_t)c * (D / 4) + lane);
            acc.x += v.x; acc.y += v.y; acc.z += v.z; acc.w += v.w;
        }
        i += chunk;
    }

    out[(size_t)gwarp * (D / 4) + lane] = acc;
}

extern "C" void kernel_launch(void* const* d_in, const int* in_sizes, int n_in,
                              void* d_out, int out_size) {
    const float4* mat = (const float4*)d_in[0];
    const int*    row = (const int*)d_in[1];
    const int*    col = (const int*)d_in[2];
    float4*       out = (float4*)d_out;

    const int T = 256;
    zero_cnt_kernel<<<(NC + T - 1) / T, T>>>();
    hist_kernel<<<(NNZ + T - 1) / T, T>>>(row);
    scan_blocksum_kernel<<<SCAN_NB, SCAN_T>>>();
    scan_toplevel_kernel<<<1, 256>>>();
    scan_final_kernel<<<SCAN_NB, SCAN_T>>>();
    scatter_idx_kernel<<<(NNZ + T - 1) / T, T>>>(row, col);

    // 100000 warps, 8 warps per block
    const long long total_threads = (long long)NC * 32;
    gather_sum_kernel<<<(int)((total_threads + T - 1) / T), T>>>(mat, out);
}

// round 3
// speedup vs baseline: 1.6362x; 1.1050x over previous
#include <cuda_runtime.h>
#include <cuda_bf16.h>
#include <cstdint>

#define NC  100000
#define NT  100000
#define NNZ 640000
#define D   128
#define CAP 32          // bucket capacity per row (avg 6.4 nnz/row, Poisson)

// ---- device-global scratch (no allocation allowed) ----
__device__ int  g_cnt[NC];            // per-row nnz count
__device__ int  g_bucket[NC * CAP];   // col indices, bucketed by row (~12.8 MB)
__device__ int  g_ovf_cnt;            // overflow entry count
__device__ int2 g_ovf[NNZ];           // overflow (row, col) pairs — worst case

// Phase 1 (fused hist+scatter): drop each nonzero's col index into its row's
// bucket slot. Overflow (slot >= CAP) spills to a list handled by phase 3.
__global__ __launch_bounds__(256) void bucket_kernel(
    const int* __restrict__ row, const int* __restrict__ col) {
    int i = blockIdx.x * blockDim.x + threadIdx.x;
    if (i >= NNZ) return;
    int r = row[i];
    int c = col[i];
    int slot = atomicAdd(&g_cnt[r], 1);
    if (slot < CAP) {
        g_bucket[r * CAP + slot] = c;
    } else {
        int p = atomicAdd(&g_ovf_cnt, 1);
        g_ovf[p] = make_int2(r, c);
    }
}

// Phase 2: one warp per output row. Each lane owns one float4 of the D=128
// row. Lane l preloads bucket col l; shfl-broadcast drives up to 32
// independent float4 gathers; single plain store (covers zero rows too).
__global__ __launch_bounds__(256) void gather_sum_kernel(
    const float4* __restrict__ mat, float4* __restrict__ out) {
    int r    = (blockIdx.x * blockDim.x + threadIdx.x) >> 5;
    int lane = threadIdx.x & 31;
    if (r >= NC) return;

    int n = g_cnt[r];
    if (n > CAP) n = CAP;

    int cj = (lane < n) ? __ldg(g_bucket + r * CAP + lane) : 0;

    float4 acc = make_float4(0.f, 0.f, 0.f, 0.f);
    #pragma unroll 4
    for (int j = 0; j < n; ++j) {
        int c = __shfl_sync(0xffffffffu, cj, j);
        float4 v = __ldg(mat + (size_t)c * (D / 4) + lane);
        acc.x += v.x; acc.y += v.y; acc.z += v.z; acc.w += v.w;
    }

    out[(size_t)r * (D / 4) + lane] = acc;
}

// Phase 3: apply overflow entries (expected count: 0) with vector red.add.
// Runs after gather's plain stores, so ordering is safe.
__global__ __launch_bounds__(256) void overflow_kernel(
    const float4* __restrict__ mat, float4* __restrict__ out) {
    int warp  = (blockIdx.x * blockDim.x + threadIdx.x) >> 5;
    int lane  = threadIdx.x & 31;
    int nwarp = (gridDim.x * blockDim.x) >> 5;
    int cnt   = g_ovf_cnt;
    if (cnt > NNZ) cnt = NNZ;
    for (int i = warp; i < cnt; i += nwarp) {
        int2 e = g_ovf[i];
        float4 v = __ldg(mat + (size_t)e.y * (D / 4) + lane);
        float* dst = reinterpret_cast<float*>(out) + (size_t)e.x * D + lane * 4;
        asm volatile(
            "red.global.add.v4.f32 [%0], {%1, %2, %3, %4};"
            :: "l"(dst), "f"(v.x), "f"(v.y), "f"(v.z), "f"(v.w)
            : "memory");
    }
}

extern "C" void kernel_launch(void* const* d_in, const int* in_sizes, int n_in,
                              void* d_out, int out_size) {
    const float4* mat = (const float4*)d_in[0];
    const int*    row = (const int*)d_in[1];
    const int*    col = (const int*)d_in[2];
    float4*       out = (float4*)d_out;

    // Zero the counters via memset nodes (graph-capturable, cheaper than a
    // zeroing kernel).
    void* cnt_ptr = nullptr;
    void* ovf_ptr = nullptr;
    cudaGetSymbolAddress(&cnt_ptr, g_cnt);
    cudaGetSymbolAddress(&ovf_ptr, g_ovf_cnt);
    cudaMemsetAsync(cnt_ptr, 0, (size_t)NC * sizeof(int));
    cudaMemsetAsync(ovf_ptr, 0, sizeof(int));

    const int T = 256;
    bucket_kernel<<<(NNZ + T - 1) / T, T>>>(row, col);

    const long long total_threads = (long long)NC * 32;
    gather_sum_kernel<<<(int)((total_threads + T - 1) / T), T>>>(mat, out);

    overflow_kernel<<<64, T>>>(mat, out);
}